// round 10
// baseline (speedup 1.0000x reference)
#include <cuda_runtime.h>
#include <cuda_bf16.h>
#include <cstdint>

#define T_STEPS 4096
#define IDIM    512
#define HDIM    2048
#define ODIM    512
#define G4H     (4 * HDIM)   // 8192

#define NCTA 148   // persistent CTAs, 1 per SM (co-resident: smem forces occ=1)
#define JPC  14    // h-indices per CTA: 148*14 = 2072 >= 2048
#define RPC  56    // rows of W_hh per CTA (4 gates * JPC)
#define RPW  7     // rows per warp (8 warps)
#define TPB  256

// -------- persistent device state (no cudaMalloc allowed) --------
__device__ __align__(16) float g_xz[(size_t)T_STEPS * G4H];  // 128 MB precomputed input projections
__device__ __align__(16) float g_h[2][HDIM];                 // double-buffered hidden state
__device__ unsigned int g_bar;                               // grid barrier counter (reset by gemm kernel)

// ---------------------------------------------------------------------------
// Kernel 1: xz[t, :] = input_seq[t, :] @ W_ih^T + (b_ih + b_hh)
// Plain fp32 SIMT GEMM, 128x128 block tile, 8x8 per thread, BK=8.
// ---------------------------------------------------------------------------
__global__ __launch_bounds__(256) void xz_gemm(const float* __restrict__ A,
                                               const float* __restrict__ W,
                                               const float* __restrict__ b1,
                                               const float* __restrict__ b2) {
    if (blockIdx.x == 0 && blockIdx.y == 0 && threadIdx.x == 0) g_bar = 0u;  // reset barrier for lstm kernel

    __shared__ float a_sm[8][128];
    __shared__ float b_sm[8][128];

    const int tid = threadIdx.x;
    const int m0 = blockIdx.y * 128;
    const int n0 = blockIdx.x * 128;

    const int lr = tid >> 1;          // 0..127 row within tile
    const int lk = (tid & 1) * 4;     // 0 or 4
    const float* Ap = A + (size_t)(m0 + lr) * IDIM + lk;
    const float* Wp = W + (size_t)(n0 + lr) * IDIM + lk;

    const int tx = tid & 15;          // n sub-tile
    const int ty = tid >> 4;          // m sub-tile

    float acc[8][8];
#pragma unroll
    for (int i = 0; i < 8; i++)
#pragma unroll
        for (int j = 0; j < 8; j++) acc[i][j] = 0.f;

    for (int k0 = 0; k0 < IDIM; k0 += 8) {
        float4 av = *(const float4*)(Ap + k0);
        float4 wv = *(const float4*)(Wp + k0);
        __syncthreads();
        a_sm[lk + 0][lr] = av.x; a_sm[lk + 1][lr] = av.y;
        a_sm[lk + 2][lr] = av.z; a_sm[lk + 3][lr] = av.w;
        b_sm[lk + 0][lr] = wv.x; b_sm[lk + 1][lr] = wv.y;
        b_sm[lk + 2][lr] = wv.z; b_sm[lk + 3][lr] = wv.w;
        __syncthreads();
#pragma unroll
        for (int kk = 0; kk < 8; kk++) {
            float ar[8], br[8];
            *(float4*)&ar[0] = *(const float4*)&a_sm[kk][ty * 8];
            *(float4*)&ar[4] = *(const float4*)&a_sm[kk][ty * 8 + 4];
            *(float4*)&br[0] = *(const float4*)&b_sm[kk][tx * 8];
            *(float4*)&br[4] = *(const float4*)&b_sm[kk][tx * 8 + 4];
#pragma unroll
            for (int i = 0; i < 8; i++)
#pragma unroll
                for (int j = 0; j < 8; j++) acc[i][j] += ar[i] * br[j];
        }
    }

    // epilogue: add combined bias, vector stores
    float bias[8];
#pragma unroll
    for (int j = 0; j < 8; j++) {
        int n = n0 + tx * 8 + j;
        bias[j] = b1[n] + b2[n];
    }
#pragma unroll
    for (int i = 0; i < 8; i++) {
        int m = m0 + ty * 8 + i;
        float* Crow = g_xz + (size_t)m * G4H + n0 + tx * 8;
        float4 o0 = make_float4(acc[i][0] + bias[0], acc[i][1] + bias[1],
                                acc[i][2] + bias[2], acc[i][3] + bias[3]);
        float4 o1 = make_float4(acc[i][4] + bias[4], acc[i][5] + bias[5],
                                acc[i][6] + bias[6], acc[i][7] + bias[7]);
        *(float4*)(Crow + 0) = o0;
        *(float4*)(Crow + 4) = o1;
    }
}

// ---------------------------------------------------------------------------
// Kernel 2: persistent LSTM recurrence. W_hh lives chip-wide in SMEM as bf16.
// Inner loop uses packed fma.rn.f32x2 (FFMA2). Barrier: tid0-only poll with
// nanosleep backoff (keeps same-address L2 poll demand below LTS service rate),
// broadcast via bar.sync.
// ---------------------------------------------------------------------------
__device__ __forceinline__ float sigmoidf_fast(float x) { return 1.f / (1.f + __expf(-x)); }
__device__ __forceinline__ float tanh_fast(float x) {
    float ax = fminf(fmaxf(x, -15.f), 15.f);
    float e = __expf(2.f * ax);
    return (e - 1.f) / (e + 1.f);
}

__device__ __forceinline__ unsigned long long ffma2(unsigned long long a,
                                                    unsigned long long b,
                                                    unsigned long long c) {
    unsigned long long d;
    asm("fma.rn.f32x2 %0, %1, %2, %3;" : "=l"(d) : "l"(a), "l"(b), "l"(c));
    return d;
}
__device__ __forceinline__ unsigned long long pack2(float lo, float hi) {
    unsigned long long r;
    asm("mov.b64 %0, {%1, %2};" : "=l"(r) : "f"(lo), "f"(hi));
    return r;
}
// bf16 pair (packed in u32) -> f32x2 pair: low bf16 -> low f32, high bf16 -> high f32
__device__ __forceinline__ unsigned long long unpack_bf2(unsigned u) {
    unsigned lo = u << 16;
    unsigned hi = u & 0xffff0000u;
    unsigned long long r;
    asm("mov.b64 %0, {%1, %2};" : "=l"(r) : "r"(lo), "r"(hi));
    return r;
}
__device__ __forceinline__ float2 unpack_f2(unsigned long long p) {
    float lo, hi;
    asm("mov.b64 {%0, %1}, %2;" : "=f"(lo), "=f"(hi) : "l"(p));
    return make_float2(lo, hi);
}

extern __shared__ __align__(16) unsigned char smem_dyn[];

__global__ __launch_bounds__(TPB, 1) void lstm_rec(const float* __restrict__ Whh) {
    __nv_bfloat16* w_sm = (__nv_bfloat16*)smem_dyn;                       // [RPC][HDIM] bf16
    float* z_sm = (float*)(smem_dyn + (size_t)RPC * HDIM * 2);            // [RPC] fp32

    const int b = blockIdx.x;
    const int tid = threadIdx.x;
    const int warp = tid >> 5;
    const int lane = tid & 31;
    const int jbase = b * JPC;

    // ---- prologue: convert our 56 W_hh rows fp32 -> bf16 into smem ----
    for (int r = 0; r < RPC; r++) {
        int gate = r / JPC;
        int jl = r - gate * JPC;
        int j = jbase + jl;
        __nv_bfloat162* dst = (__nv_bfloat162*)(w_sm + (size_t)r * HDIM);
        if (j < HDIM) {
            const float4* src = (const float4*)(Whh + (size_t)(gate * HDIM + j) * HDIM);
            for (int i = tid; i < HDIM / 4; i += TPB) {
                float4 v = src[i];
                dst[2 * i]     = __floats2bfloat162_rn(v.x, v.y);
                dst[2 * i + 1] = __floats2bfloat162_rn(v.z, v.w);
            }
        } else {
            for (int i = tid; i < HDIM / 2; i += TPB)
                dst[i] = __floats2bfloat162_rn(0.f, 0.f);
        }
    }
    // zero initial hidden state slice (buffer 0 is read at t=0)
    if (tid < JPC && jbase + tid < HDIM) g_h[0][jbase + tid] = 0.f;

    // per-lane xz source pointer (row this lane owns in the z assembly)
    const int myrow = warp * RPW + lane;  // valid only when lane < RPW
    bool xz_valid = false;
    const float* xzp = g_xz;
    if (lane < RPW) {
        int gate = myrow / JPC;
        int jl = myrow - gate * JPC;
        int j = jbase + jl;
        if (j < HDIM) { xz_valid = true; xzp = g_xz + (size_t)gate * HDIM + j; }
    }

    float c_state = 0.f;
    unsigned int phase = 0;

    // prefetch xz for t=0 (g_xz fully written by the preceding gemm kernel)
    float xzv = xz_valid ? __ldcg(xzp) : 0.f;

    // prologue grid barrier: h zeros + weights visible everywhere before step 0
    phase += NCTA;
    __syncthreads();
    if (tid == 0) {
        __threadfence();
        atomicAdd(&g_bar, 1u);
        unsigned int v;
        do {
            asm volatile("ld.acquire.gpu.u32 %0, [%1];" : "=r"(v) : "l"(&g_bar));
            if (v >= phase) break;
            __nanosleep(32);
        } while (true);
    }
    __syncthreads();

    for (int t = 0; t < T_STEPS; t++) {
        const float* hin = g_h[t & 1];

        // prefetch next step's xz early: DRAM latency hidden under the matvec
        float xzv_next = 0.f;
        if (xz_valid && t + 1 < T_STEPS)
            xzv_next = __ldcg(xzp + (size_t)(t + 1) * G4H);

        // load this lane's 64 h values (cols lane*8 + 256*c .. +8) via L2
        float4 hv[16];
#pragma unroll
        for (int c = 0; c < 8; c++) {
            const float4* hp = (const float4*)hin + (lane * 2 + c * 64);
            hv[2 * c]     = __ldcg(hp);
            hv[2 * c + 1] = __ldcg(hp + 1);
        }

        unsigned long long accp[RPW];
#pragma unroll
        for (int r = 0; r < RPW; r++) accp[r] = 0ull;

        const uint4* wbase = (const uint4*)w_sm;  // 8 bf16 per uint4; row = 256 uint4
#pragma unroll
        for (int c = 0; c < 8; c++) {             // c outer: interleaves the 7 FMA chains
            float4 h0 = hv[2 * c];
            float4 h1 = hv[2 * c + 1];
            unsigned long long hp0 = pack2(h0.x, h0.y);
            unsigned long long hp1 = pack2(h0.z, h0.w);
            unsigned long long hp2 = pack2(h1.x, h1.y);
            unsigned long long hp3 = pack2(h1.z, h1.w);
#pragma unroll
            for (int r = 0; r < RPW; r++) {
                uint4 u = wbase[(warp * RPW + r) * 256 + lane + 32 * c];
                unsigned long long a = accp[r];
                a = ffma2(unpack_bf2(u.x), hp0, a);
                a = ffma2(unpack_bf2(u.y), hp1, a);
                a = ffma2(unpack_bf2(u.z), hp2, a);
                a = ffma2(unpack_bf2(u.w), hp3, a);
                accp[r] = a;
            }
        }

        // collapse pairs, then warp butterfly reduce each of the 7 row partials
        float acc[RPW];
#pragma unroll
        for (int r = 0; r < RPW; r++) {
            float2 p = unpack_f2(accp[r]);
            float a = p.x + p.y;
#pragma unroll
            for (int off = 16; off; off >>= 1)
                a += __shfl_xor_sync(0xffffffffu, a, off);
            acc[r] = a;
        }

        if (lane < RPW) {
            float z = xzv;
#pragma unroll
            for (int r = 0; r < RPW; r++)
                if (lane == r) z += acc[r];
            z_sm[myrow] = z;
        }
        __syncthreads();   // z_sm complete before gate math reads it

        // gate math + state update for our 14 h-indices (warp 0 only)
        if (tid < JPC) {
            int j = jbase + tid;
            if (j < HDIM) {
                float zi = z_sm[tid];
                float zf = z_sm[JPC + tid];
                float zg = z_sm[2 * JPC + tid];
                float zo = z_sm[3 * JPC + tid];
                float ig = sigmoidf_fast(zi);
                float fg = sigmoidf_fast(zf);
                float gg = tanh_fast(zg);
                float og = sigmoidf_fast(zo);
                c_state = fg * c_state + ig * gg;
                g_h[(t + 1) & 1][j] = og * tanh_fast(c_state);
            }
        }

        // grid barrier: tid0-only poll with backoff, bar.sync broadcast.
        phase += NCTA;
        __syncthreads();
        if (tid == 0) {
            __threadfence();
            atomicAdd(&g_bar, 1u);
            unsigned int v;
            do {
                asm volatile("ld.acquire.gpu.u32 %0, [%1];" : "=r"(v) : "l"(&g_bar));
                if (v >= phase) break;
                __nanosleep(32);
            } while (true);
        }
        __syncthreads();

        xzv = xzv_next;
    }
}

// ---------------------------------------------------------------------------
// Kernel 3: out = W_lin @ h_T + b_lin   (h_T is in g_h[0]: (4095+1)&1 == 0)
// ---------------------------------------------------------------------------
__global__ __launch_bounds__(256) void final_linear(const float* __restrict__ Wlin,
                                                    const float* __restrict__ blin,
                                                    float* __restrict__ out) {
    const float* h = g_h[0];
    const int o = blockIdx.x;
    const int tid = threadIdx.x;
    const float* wr = Wlin + (size_t)o * HDIM;

    float s = 0.f;
    for (int j = tid; j < HDIM; j += 256) s += wr[j] * h[j];

    __shared__ float red[8];
#pragma unroll
    for (int off = 16; off; off >>= 1) s += __shfl_xor_sync(0xffffffffu, s, off);
    if ((tid & 31) == 0) red[tid >> 5] = s;
    __syncthreads();
    if (tid < 32) {
        float v = (tid < 8) ? red[tid] : 0.f;
#pragma unroll
        for (int off = 16; off; off >>= 1) v += __shfl_xor_sync(0xffffffffu, v, off);
        if (tid == 0) out[o] = v + blin[o];
    }
}

// ---------------------------------------------------------------------------
extern "C" void kernel_launch(void* const* d_in, const int* in_sizes, int n_in,
                              void* d_out, int out_size) {
    const float* x    = (const float*)d_in[0];
    const float* Wih  = (const float*)d_in[1];
    const float* Whh  = (const float*)d_in[2];
    const float* bih  = (const float*)d_in[3];
    const float* bhh  = (const float*)d_in[4];
    const float* Wlin = (const float*)d_in[5];
    const float* blin = (const float*)d_in[6];
    float* out = (float*)d_out;

    const size_t smem = (size_t)RPC * HDIM * 2 + RPC * 4;  // 229,376 + 224 = 229,600 B
    cudaFuncSetAttribute(lstm_rec, cudaFuncAttributeMaxDynamicSharedMemorySize, (int)smem);

    dim3 gg(G4H / 128, T_STEPS / 128);
    xz_gemm<<<gg, 256>>>(x, Wih, bih, bhh);        // also resets g_bar
    lstm_rec<<<NCTA, TPB, smem>>>(Whh);
    final_linear<<<ODIM, 256>>>(Wlin, blin, out);
}

// round 11
// speedup vs baseline: 1.3098x; 1.3098x over previous
#include <cuda_runtime.h>
#include <cuda_bf16.h>
#include <cstdint>

#define T_STEPS 4096
#define IDIM    512
#define HDIM    2048
#define ODIM    512
#define G4H     (4 * HDIM)   // 8192

#define NCTA 148   // persistent CTAs, 1 per SM (co-resident: smem forces occ=1)
#define JPC  14    // h-indices per CTA: 148*14 = 2072 >= 2048
#define RPC  56    // rows of W_hh per CTA (4 gates * JPC)
#define RPW  7     // rows per warp (8 warps)
#define TPB  256

// -------- persistent device state (no cudaMalloc allowed) --------
__device__ __align__(16) float g_xz[(size_t)T_STEPS * G4H];  // 128 MB precomputed input projections
__device__ __align__(16) float g_h[2][HDIM];                 // double-buffered hidden state
__device__ unsigned int g_bar;                               // grid barrier counter (reset by gemm kernel)

// ---------------------------------------------------------------------------
// Kernel 1: xz[t, :] = input_seq[t, :] @ W_ih^T + (b_ih + b_hh)
// Plain fp32 SIMT GEMM, 128x128 block tile, 8x8 per thread, BK=8.
// ---------------------------------------------------------------------------
__global__ __launch_bounds__(256) void xz_gemm(const float* __restrict__ A,
                                               const float* __restrict__ W,
                                               const float* __restrict__ b1,
                                               const float* __restrict__ b2) {
    if (blockIdx.x == 0 && blockIdx.y == 0 && threadIdx.x == 0) g_bar = 0u;  // reset barrier for lstm kernel

    __shared__ float a_sm[8][128];
    __shared__ float b_sm[8][128];

    const int tid = threadIdx.x;
    const int m0 = blockIdx.y * 128;
    const int n0 = blockIdx.x * 128;

    const int lr = tid >> 1;          // 0..127 row within tile
    const int lk = (tid & 1) * 4;     // 0 or 4
    const float* Ap = A + (size_t)(m0 + lr) * IDIM + lk;
    const float* Wp = W + (size_t)(n0 + lr) * IDIM + lk;

    const int tx = tid & 15;          // n sub-tile
    const int ty = tid >> 4;          // m sub-tile

    float acc[8][8];
#pragma unroll
    for (int i = 0; i < 8; i++)
#pragma unroll
        for (int j = 0; j < 8; j++) acc[i][j] = 0.f;

    for (int k0 = 0; k0 < IDIM; k0 += 8) {
        float4 av = *(const float4*)(Ap + k0);
        float4 wv = *(const float4*)(Wp + k0);
        __syncthreads();
        a_sm[lk + 0][lr] = av.x; a_sm[lk + 1][lr] = av.y;
        a_sm[lk + 2][lr] = av.z; a_sm[lk + 3][lr] = av.w;
        b_sm[lk + 0][lr] = wv.x; b_sm[lk + 1][lr] = wv.y;
        b_sm[lk + 2][lr] = wv.z; b_sm[lk + 3][lr] = wv.w;
        __syncthreads();
#pragma unroll
        for (int kk = 0; kk < 8; kk++) {
            float ar[8], br[8];
            *(float4*)&ar[0] = *(const float4*)&a_sm[kk][ty * 8];
            *(float4*)&ar[4] = *(const float4*)&a_sm[kk][ty * 8 + 4];
            *(float4*)&br[0] = *(const float4*)&b_sm[kk][tx * 8];
            *(float4*)&br[4] = *(const float4*)&b_sm[kk][tx * 8 + 4];
#pragma unroll
            for (int i = 0; i < 8; i++)
#pragma unroll
                for (int j = 0; j < 8; j++) acc[i][j] += ar[i] * br[j];
        }
    }

    // epilogue: add combined bias, vector stores
    float bias[8];
#pragma unroll
    for (int j = 0; j < 8; j++) {
        int n = n0 + tx * 8 + j;
        bias[j] = b1[n] + b2[n];
    }
#pragma unroll
    for (int i = 0; i < 8; i++) {
        int m = m0 + ty * 8 + i;
        float* Crow = g_xz + (size_t)m * G4H + n0 + tx * 8;
        float4 o0 = make_float4(acc[i][0] + bias[0], acc[i][1] + bias[1],
                                acc[i][2] + bias[2], acc[i][3] + bias[3]);
        float4 o1 = make_float4(acc[i][4] + bias[4], acc[i][5] + bias[5],
                                acc[i][6] + bias[6], acc[i][7] + bias[7]);
        *(float4*)(Crow + 0) = o0;
        *(float4*)(Crow + 4) = o1;
    }
}

// ---------------------------------------------------------------------------
// Kernel 2: persistent LSTM recurrence. W_hh lives chip-wide in SMEM as bf16.
// Exact R6 structure (scalar FFMA mainloop); barrier spin has NO nanosleep:
// tid0-only polling = 148 pollers x 1 outstanding acquire (~0.6 req/cyc to the
// barrier's LTS, under its ~1/cyc same-address service rate), so detection
// latency is ~1 L2 round trip instead of a sleep quantum.
// ---------------------------------------------------------------------------
__device__ __forceinline__ float bf_lo(unsigned u) { return __uint_as_float(u << 16); }
__device__ __forceinline__ float bf_hi(unsigned u) { return __uint_as_float(u & 0xffff0000u); }
__device__ __forceinline__ float sigmoidf_fast(float x) { return 1.f / (1.f + __expf(-x)); }

extern __shared__ __align__(16) unsigned char smem_dyn[];

__global__ __launch_bounds__(TPB, 1) void lstm_rec(const float* __restrict__ Whh) {
    __nv_bfloat16* w_sm = (__nv_bfloat16*)smem_dyn;                       // [RPC][HDIM] bf16
    float* z_sm = (float*)(smem_dyn + (size_t)RPC * HDIM * 2);            // [RPC] fp32

    const int b = blockIdx.x;
    const int tid = threadIdx.x;
    const int warp = tid >> 5;
    const int lane = tid & 31;
    const int jbase = b * JPC;

    // ---- prologue: convert our 56 W_hh rows fp32 -> bf16 into smem ----
    for (int r = 0; r < RPC; r++) {
        int gate = r / JPC;
        int jl = r - gate * JPC;
        int j = jbase + jl;
        __nv_bfloat162* dst = (__nv_bfloat162*)(w_sm + (size_t)r * HDIM);
        if (j < HDIM) {
            const float4* src = (const float4*)(Whh + (size_t)(gate * HDIM + j) * HDIM);
            for (int i = tid; i < HDIM / 4; i += TPB) {
                float4 v = src[i];
                dst[2 * i]     = __floats2bfloat162_rn(v.x, v.y);
                dst[2 * i + 1] = __floats2bfloat162_rn(v.z, v.w);
            }
        } else {
            for (int i = tid; i < HDIM / 2; i += TPB)
                dst[i] = __floats2bfloat162_rn(0.f, 0.f);
        }
    }
    // zero initial hidden state slice (buffer 0 is read at t=0)
    if (tid < JPC && jbase + tid < HDIM) g_h[0][jbase + tid] = 0.f;

    float c_state = 0.f;
    unsigned int phase = 0;

    // prologue grid barrier: h zeros visible everywhere before step 0
    phase += NCTA;
    __syncthreads();
    if (tid == 0) {
        __threadfence();
        atomicAdd(&g_bar, 1u);
        unsigned int v;
        do {
            asm volatile("ld.acquire.gpu.u32 %0, [%1];" : "=r"(v) : "l"(&g_bar));
        } while (v < phase);
    }
    __syncthreads();

    const int myrow = warp * RPW + lane;  // valid when lane < RPW

    for (int t = 0; t < T_STEPS; t++) {
        const float* hin = g_h[t & 1];

        // this step's xz value for the row this lane will own (lane<7)
        float xzv = 0.f;
        if (lane < RPW) {
            int gate = myrow / JPC;
            int jl = myrow - gate * JPC;
            int j = jbase + jl;
            if (j < HDIM)
                xzv = __ldcg(&g_xz[(size_t)t * G4H + gate * HDIM + j]);
        }

        // load this lane's 64 h values (cols lane*8 + 256*c .. +8) via L2
        float4 hv[16];
#pragma unroll
        for (int c = 0; c < 8; c++) {
            const float4* hp = (const float4*)hin + (lane * 2 + c * 64);
            hv[2 * c]     = __ldcg(hp);
            hv[2 * c + 1] = __ldcg(hp + 1);
        }

        float acc[RPW];
#pragma unroll
        for (int r = 0; r < RPW; r++) acc[r] = 0.f;

        const uint4* wbase = (const uint4*)w_sm;  // 8 bf16 per uint4; row = 256 uint4
#pragma unroll
        for (int c = 0; c < 8; c++) {             // c outer: interleaves the 7 FMA chains
            float4 h0 = hv[2 * c];
            float4 h1 = hv[2 * c + 1];
#pragma unroll
            for (int r = 0; r < RPW; r++) {
                uint4 u = wbase[(warp * RPW + r) * 256 + lane + 32 * c];
                float a = acc[r];
                a += bf_lo(u.x) * h0.x; a += bf_hi(u.x) * h0.y;
                a += bf_lo(u.y) * h0.z; a += bf_hi(u.y) * h0.w;
                a += bf_lo(u.z) * h1.x; a += bf_hi(u.z) * h1.y;
                a += bf_lo(u.w) * h1.z; a += bf_hi(u.w) * h1.w;
                acc[r] = a;
            }
        }

        // warp butterfly reduce each of the 7 row partials
#pragma unroll
        for (int r = 0; r < RPW; r++) {
            float a = acc[r];
#pragma unroll
            for (int off = 16; off; off >>= 1)
                a += __shfl_xor_sync(0xffffffffu, a, off);
            acc[r] = a;
        }

        if (lane < RPW) {
            float z = xzv;
#pragma unroll
            for (int r = 0; r < RPW; r++)
                if (lane == r) z += acc[r];
            z_sm[myrow] = z;
        }
        __syncthreads();

        // gate math + state update for our 14 h-indices
        if (tid < JPC) {
            int j = jbase + tid;
            if (j < HDIM) {
                float zi = z_sm[tid];
                float zf = z_sm[JPC + tid];
                float zg = z_sm[2 * JPC + tid];
                float zo = z_sm[3 * JPC + tid];
                float ig = sigmoidf_fast(zi);
                float fg = sigmoidf_fast(zf);
                float gg = tanhf(zg);
                float og = sigmoidf_fast(zo);
                c_state = fg * c_state + ig * gg;
                g_h[(t + 1) & 1][j] = og * tanhf(c_state);
            }
        }

        // grid barrier (monotonic counter, release via fence, tid0 busy-poll)
        phase += NCTA;
        __syncthreads();
        if (tid == 0) {
            __threadfence();
            atomicAdd(&g_bar, 1u);
            unsigned int v;
            do {
                asm volatile("ld.acquire.gpu.u32 %0, [%1];" : "=r"(v) : "l"(&g_bar));
            } while (v < phase);
        }
        __syncthreads();
    }
}

// ---------------------------------------------------------------------------
// Kernel 3: out = W_lin @ h_T + b_lin   (h_T is in g_h[0]: (4095+1)&1 == 0)
// ---------------------------------------------------------------------------
__global__ __launch_bounds__(256) void final_linear(const float* __restrict__ Wlin,
                                                    const float* __restrict__ blin,
                                                    float* __restrict__ out) {
    const float* h = g_h[0];
    const int o = blockIdx.x;
    const int tid = threadIdx.x;
    const float* wr = Wlin + (size_t)o * HDIM;

    float s = 0.f;
    for (int j = tid; j < HDIM; j += 256) s += wr[j] * h[j];

    __shared__ float red[8];
#pragma unroll
    for (int off = 16; off; off >>= 1) s += __shfl_xor_sync(0xffffffffu, s, off);
    if ((tid & 31) == 0) red[tid >> 5] = s;
    __syncthreads();
    if (tid < 32) {
        float v = (tid < 8) ? red[tid] : 0.f;
#pragma unroll
        for (int off = 16; off; off >>= 1) v += __shfl_xor_sync(0xffffffffu, v, off);
        if (tid == 0) out[o] = v + blin[o];
    }
}

// ---------------------------------------------------------------------------
extern "C" void kernel_launch(void* const* d_in, const int* in_sizes, int n_in,
                              void* d_out, int out_size) {
    const float* x    = (const float*)d_in[0];
    const float* Wih  = (const float*)d_in[1];
    const float* Whh  = (const float*)d_in[2];
    const float* bih  = (const float*)d_in[3];
    const float* bhh  = (const float*)d_in[4];
    const float* Wlin = (const float*)d_in[5];
    const float* blin = (const float*)d_in[6];
    float* out = (float*)d_out;

    const size_t smem = (size_t)RPC * HDIM * 2 + RPC * 4;  // 229,376 + 224 = 229,600 B
    cudaFuncSetAttribute(lstm_rec, cudaFuncAttributeMaxDynamicSharedMemorySize, (int)smem);

    dim3 gg(G4H / 128, T_STEPS / 128);
    xz_gemm<<<gg, 256>>>(x, Wih, bih, bhh);        // also resets g_bar
    lstm_rec<<<NCTA, TPB, smem>>>(Whh);
    final_linear<<<ODIM, 256>>>(Wlin, blin, out);
}

// round 12
// speedup vs baseline: 1.8623x; 1.4218x over previous
#include <cuda_runtime.h>
#include <cuda_bf16.h>
#include <cstdint>

#define T_STEPS 4096
#define IDIM    512
#define HDIM    2048
#define ODIM    512
#define G4H     (4 * HDIM)   // 8192

#define NCTA 148   // persistent CTAs, 1 per SM (co-resident: smem forces occ=1)
#define JPC  14    // h-indices per CTA: 148*14 = 2072 >= 2048
#define RPC  56    // rows of W_hh per CTA (4 gates * JPC)
#define RPW  7     // rows per warp (8 warps); 6 rows in smem + 1 row in registers
#define SROWS_PER_WARP 6
#define NSMEM_ROWS (8 * SROWS_PER_WARP)   // 48
#define TPB  256

// -------- persistent device state (no cudaMalloc allowed) --------
__device__ __align__(16) float g_xz[(size_t)T_STEPS * G4H];  // 128 MB precomputed input projections
__device__ __align__(16) float g_h[2][HDIM];                 // double-buffered hidden state
__device__ unsigned int g_bar;                               // grid barrier counter (reset by gemm kernel)

// ---------------------------------------------------------------------------
// Kernel 1: xz[t, :] = input_seq[t, :] @ W_ih^T + (b_ih + b_hh)
// Plain fp32 SIMT GEMM, 128x128 block tile, 8x8 per thread, BK=8.
// ---------------------------------------------------------------------------
__global__ __launch_bounds__(256) void xz_gemm(const float* __restrict__ A,
                                               const float* __restrict__ W,
                                               const float* __restrict__ b1,
                                               const float* __restrict__ b2) {
    if (blockIdx.x == 0 && blockIdx.y == 0 && threadIdx.x == 0) g_bar = 0u;  // reset barrier for lstm kernel

    __shared__ float a_sm[8][128];
    __shared__ float b_sm[8][128];

    const int tid = threadIdx.x;
    const int m0 = blockIdx.y * 128;
    const int n0 = blockIdx.x * 128;

    const int lr = tid >> 1;          // 0..127 row within tile
    const int lk = (tid & 1) * 4;     // 0 or 4
    const float* Ap = A + (size_t)(m0 + lr) * IDIM + lk;
    const float* Wp = W + (size_t)(n0 + lr) * IDIM + lk;

    const int tx = tid & 15;          // n sub-tile
    const int ty = tid >> 4;          // m sub-tile

    float acc[8][8];
#pragma unroll
    for (int i = 0; i < 8; i++)
#pragma unroll
        for (int j = 0; j < 8; j++) acc[i][j] = 0.f;

    for (int k0 = 0; k0 < IDIM; k0 += 8) {
        float4 av = *(const float4*)(Ap + k0);
        float4 wv = *(const float4*)(Wp + k0);
        __syncthreads();
        a_sm[lk + 0][lr] = av.x; a_sm[lk + 1][lr] = av.y;
        a_sm[lk + 2][lr] = av.z; a_sm[lk + 3][lr] = av.w;
        b_sm[lk + 0][lr] = wv.x; b_sm[lk + 1][lr] = wv.y;
        b_sm[lk + 2][lr] = wv.z; b_sm[lk + 3][lr] = wv.w;
        __syncthreads();
#pragma unroll
        for (int kk = 0; kk < 8; kk++) {
            float ar[8], br[8];
            *(float4*)&ar[0] = *(const float4*)&a_sm[kk][ty * 8];
            *(float4*)&ar[4] = *(const float4*)&a_sm[kk][ty * 8 + 4];
            *(float4*)&br[0] = *(const float4*)&b_sm[kk][tx * 8];
            *(float4*)&br[4] = *(const float4*)&b_sm[kk][tx * 8 + 4];
#pragma unroll
            for (int i = 0; i < 8; i++)
#pragma unroll
                for (int j = 0; j < 8; j++) acc[i][j] += ar[i] * br[j];
        }
    }

    // epilogue: add combined bias, vector stores
    float bias[8];
#pragma unroll
    for (int j = 0; j < 8; j++) {
        int n = n0 + tx * 8 + j;
        bias[j] = b1[n] + b2[n];
    }
#pragma unroll
    for (int i = 0; i < 8; i++) {
        int m = m0 + ty * 8 + i;
        float* Crow = g_xz + (size_t)m * G4H + n0 + tx * 8;
        float4 o0 = make_float4(acc[i][0] + bias[0], acc[i][1] + bias[1],
                                acc[i][2] + bias[2], acc[i][3] + bias[3]);
        float4 o1 = make_float4(acc[i][4] + bias[4], acc[i][5] + bias[5],
                                acc[i][6] + bias[6], acc[i][7] + bias[7]);
        *(float4*)(Crow + 0) = o0;
        *(float4*)(Crow + 4) = o1;
    }
}

// ---------------------------------------------------------------------------
// Kernel 2: persistent LSTM recurrence.
//  - 48 of 56 W_hh rows (bf16) in SMEM, 1 row/warp in registers (32 uint/lane)
//  - h staged through SMEM once per CTA (512 LDG.128 instead of 4096 -> L1tex
//    wavefront queue drain drops ~4000 cyc -> ~500 cyc, and 8x less L2 fanout)
//  - tid0-only barrier poll with nanosleep backoff (best-known config)
// ---------------------------------------------------------------------------
__device__ __forceinline__ float bf_lo(unsigned u) { return __uint_as_float(u << 16); }
__device__ __forceinline__ float bf_hi(unsigned u) { return __uint_as_float(u & 0xffff0000u); }
__device__ __forceinline__ float sigmoidf_fast(float x) { return 1.f / (1.f + __expf(-x)); }
__device__ __forceinline__ float tanh_fast(float x) {
    float ax = fminf(fmaxf(x, -15.f), 15.f);
    float e = __expf(2.f * ax);
    return (e - 1.f) / (e + 1.f);
}

extern __shared__ __align__(16) unsigned char smem_dyn[];

__global__ __launch_bounds__(TPB, 1) void lstm_rec(const float* __restrict__ Whh) {
    // layout: weights (48 rows x 2048 bf16 = 196,608 B) | h stage (8,192 B) | z (224 B)
    __nv_bfloat16* w_sm = (__nv_bfloat16*)smem_dyn;
    float* h_sm = (float*)(smem_dyn + (size_t)NSMEM_ROWS * HDIM * 2);
    float* z_sm = h_sm + HDIM;

    const int b = blockIdx.x;
    const int tid = threadIdx.x;
    const int warp = tid >> 5;
    const int lane = tid & 31;
    const int jbase = b * JPC;

    // ---- prologue A: 48 smem rows (warp w slots 0..5 -> global rows w*7+0..5) ----
    for (int s = 0; s < NSMEM_ROWS; s++) {
        int w = s / SROWS_PER_WARP;
        int i = s - w * SROWS_PER_WARP;
        int r = w * RPW + i;               // global row 0..55 (skipping each warp's 7th)
        int gate = r / JPC;
        int jl = r - gate * JPC;
        int j = jbase + jl;
        __nv_bfloat162* dst = (__nv_bfloat162*)(w_sm + (size_t)s * HDIM);
        if (j < HDIM) {
            const float4* src = (const float4*)(Whh + (size_t)(gate * HDIM + j) * HDIM);
            for (int k = tid; k < HDIM / 4; k += TPB) {
                float4 v = src[k];
                dst[2 * k]     = __floats2bfloat162_rn(v.x, v.y);
                dst[2 * k + 1] = __floats2bfloat162_rn(v.z, v.w);
            }
        } else {
            for (int k = tid; k < HDIM / 2; k += TPB)
                dst[k] = __floats2bfloat162_rn(0.f, 0.f);
        }
    }

    // ---- prologue B: register row (each warp's row w*7+6); lane's 64-col slice ----
    unsigned wreg[32];
    {
        int r = warp * RPW + (RPW - 1);
        int gate = r / JPC;
        int jl = r - gate * JPC;
        int j = jbase + jl;
        if (j < HDIM) {
            const float* rowp = Whh + (size_t)(gate * HDIM + j) * HDIM;
#pragma unroll
            for (int c = 0; c < 8; c++) {
                int col0 = 8 * lane + 256 * c;
#pragma unroll
                for (int k = 0; k < 4; k++) {
                    float2 p = *(const float2*)(rowp + col0 + 2 * k);
                    __nv_bfloat162 bb = __floats2bfloat162_rn(p.x, p.y);
                    wreg[4 * c + k] = *(unsigned*)&bb;
                }
            }
        } else {
#pragma unroll
            for (int k = 0; k < 32; k++) wreg[k] = 0u;
        }
    }

    // zero initial hidden state slice (buffer 0 is read at t=0)
    if (tid < JPC && jbase + tid < HDIM) g_h[0][jbase + tid] = 0.f;

    float c_state = 0.f;
    unsigned int phase = 0;

    // prologue grid barrier: h zeros visible everywhere before step 0
    phase += NCTA;
    __syncthreads();
    if (tid == 0) {
        __threadfence();
        atomicAdd(&g_bar, 1u);
        unsigned int v;
        do {
            asm volatile("ld.acquire.gpu.u32 %0, [%1];" : "=r"(v) : "l"(&g_bar));
            if (v >= phase) break;
            __nanosleep(32);
        } while (true);
    }
    __syncthreads();

    const int myrow = warp * RPW + lane;  // valid when lane < RPW

    for (int t = 0; t < T_STEPS; t++) {
        // this step's xz value for the row this lane will own (lane<7)
        float xzv = 0.f;
        if (lane < RPW) {
            int gate = myrow / JPC;
            int jl = myrow - gate * JPC;
            int j = jbase + jl;
            if (j < HDIM)
                xzv = __ldcg(&g_xz[(size_t)t * G4H + gate * HDIM + j]);
        }

        // ---- stage h into SMEM: 2 LDG.128 per thread (512 per CTA total) ----
        {
            const float4* hg = (const float4*)g_h[t & 1];
            float4 v0 = __ldcg(hg + tid * 2);
            float4 v1 = __ldcg(hg + tid * 2 + 1);
            ((float4*)h_sm)[tid * 2]     = v0;
            ((float4*)h_sm)[tid * 2 + 1] = v1;
        }
        __syncthreads();

        float acc[RPW];
#pragma unroll
        for (int r = 0; r < RPW; r++) acc[r] = 0.f;

        const uint4* wbase = (const uint4*)w_sm;  // 8 bf16 per uint4; row = 256 uint4
#pragma unroll
        for (int c = 0; c < 8; c++) {
            float4 h0 = *(const float4*)&h_sm[c * 256 + lane * 8];
            float4 h1 = *(const float4*)&h_sm[c * 256 + lane * 8 + 4];
            // 6 smem rows
#pragma unroll
            for (int r = 0; r < SROWS_PER_WARP; r++) {
                uint4 u = wbase[(warp * SROWS_PER_WARP + r) * 256 + lane + 32 * c];
                float a = acc[r];
                a += bf_lo(u.x) * h0.x; a += bf_hi(u.x) * h0.y;
                a += bf_lo(u.y) * h0.z; a += bf_hi(u.y) * h0.w;
                a += bf_lo(u.z) * h1.x; a += bf_hi(u.z) * h1.y;
                a += bf_lo(u.w) * h1.z; a += bf_hi(u.w) * h1.w;
                acc[r] = a;
            }
            // register row (row warp*7+6)
            {
                unsigned ux = wreg[4 * c + 0], uy = wreg[4 * c + 1];
                unsigned uz = wreg[4 * c + 2], uw = wreg[4 * c + 3];
                float a = acc[RPW - 1];
                a += bf_lo(ux) * h0.x; a += bf_hi(ux) * h0.y;
                a += bf_lo(uy) * h0.z; a += bf_hi(uy) * h0.w;
                a += bf_lo(uz) * h1.x; a += bf_hi(uz) * h1.y;
                a += bf_lo(uw) * h1.z; a += bf_hi(uw) * h1.w;
                acc[RPW - 1] = a;
            }
        }

        // warp butterfly reduce each of the 7 row partials
#pragma unroll
        for (int r = 0; r < RPW; r++) {
            float a = acc[r];
#pragma unroll
            for (int off = 16; off; off >>= 1)
                a += __shfl_xor_sync(0xffffffffu, a, off);
            acc[r] = a;
        }

        if (lane < RPW) {
            float z = xzv;
#pragma unroll
            for (int r = 0; r < RPW; r++)
                if (lane == r) z += acc[r];
            z_sm[myrow] = z;
        }
        __syncthreads();   // z_sm complete before gate math reads it

        // gate math + state update for our 14 h-indices (warp 0, lanes 0..13)
        if (tid < JPC) {
            int j = jbase + tid;
            if (j < HDIM) {
                float zi = z_sm[tid];
                float zf = z_sm[JPC + tid];
                float zg = z_sm[2 * JPC + tid];
                float zo = z_sm[3 * JPC + tid];
                float ig = sigmoidf_fast(zi);
                float fg = sigmoidf_fast(zf);
                float gg = tanh_fast(zg);
                float og = sigmoidf_fast(zo);
                c_state = fg * c_state + ig * gg;
                g_h[(t + 1) & 1][j] = og * tanh_fast(c_state);
            }
        }
        __syncwarp();   // warp0: gate h-stores ordered before tid0's fence below

        // grid barrier (monotonic counter; fence-release, tid0 poll w/ backoff)
        phase += NCTA;
        if (tid == 0) {
            __threadfence();
            atomicAdd(&g_bar, 1u);
            unsigned int v;
            do {
                asm volatile("ld.acquire.gpu.u32 %0, [%1];" : "=r"(v) : "l"(&g_bar));
                if (v >= phase) break;
                __nanosleep(32);
            } while (true);
        }
        __syncthreads();   // release broadcast; also protects h_sm refill next step
    }
}

// ---------------------------------------------------------------------------
// Kernel 3: out = W_lin @ h_T + b_lin   (h_T is in g_h[0]: (4095+1)&1 == 0)
// ---------------------------------------------------------------------------
__global__ __launch_bounds__(256) void final_linear(const float* __restrict__ Wlin,
                                                    const float* __restrict__ blin,
                                                    float* __restrict__ out) {
    const float* h = g_h[0];
    const int o = blockIdx.x;
    const int tid = threadIdx.x;
    const float* wr = Wlin + (size_t)o * HDIM;

    float s = 0.f;
    for (int j = tid; j < HDIM; j += 256) s += wr[j] * h[j];

    __shared__ float red[8];
#pragma unroll
    for (int off = 16; off; off >>= 1) s += __shfl_xor_sync(0xffffffffu, s, off);
    if ((tid & 31) == 0) red[tid >> 5] = s;
    __syncthreads();
    if (tid < 32) {
        float v = (tid < 8) ? red[tid] : 0.f;
#pragma unroll
        for (int off = 16; off; off >>= 1) v += __shfl_xor_sync(0xffffffffu, v, off);
        if (tid == 0) out[o] = v + blin[o];
    }
}

// ---------------------------------------------------------------------------
extern "C" void kernel_launch(void* const* d_in, const int* in_sizes, int n_in,
                              void* d_out, int out_size) {
    const float* x    = (const float*)d_in[0];
    const float* Wih  = (const float*)d_in[1];
    const float* Whh  = (const float*)d_in[2];
    const float* bih  = (const float*)d_in[3];
    const float* bhh  = (const float*)d_in[4];
    const float* Wlin = (const float*)d_in[5];
    const float* blin = (const float*)d_in[6];
    float* out = (float*)d_out;

    // 48*2048*2 + 2048*4 + 56*4 = 196,608 + 8,192 + 224 = 205,024 B
    const size_t smem = (size_t)NSMEM_ROWS * HDIM * 2 + HDIM * 4 + RPC * 4;
    cudaFuncSetAttribute(lstm_rec, cudaFuncAttributeMaxDynamicSharedMemorySize, (int)smem);

    dim3 gg(G4H / 128, T_STEPS / 128);
    xz_gemm<<<gg, 256>>>(x, Wih, bih, bhh);        // also resets g_bar
    lstm_rec<<<NCTA, TPB, smem>>>(Whh);
    final_linear<<<ODIM, 256>>>(Wlin, blin, out);
}

// round 13
// speedup vs baseline: 1.9257x; 1.0340x over previous
#include <cuda_runtime.h>
#include <cuda_bf16.h>
#include <cstdint>

#define T_STEPS 4096
#define IDIM    512
#define HDIM    2048
#define ODIM    512
#define G4H     (4 * HDIM)   // 8192

#define NCTA 148   // persistent CTAs, 1 per SM (co-resident: smem forces occ=1)
#define JPC  14    // h-indices per CTA: 148*14 = 2072 >= 2048
#define RPC  56    // rows of W_hh per CTA (4 gates * JPC)
#define RPW  7     // rows per warp (8 warps); 4 rows in smem + 3 rows in registers
#define SROWS_PER_WARP 4
#define RROWS_PER_WARP 3
#define NSMEM_ROWS (8 * SROWS_PER_WARP)   // 32
#define TPB  256

// -------- persistent device state (no cudaMalloc allowed) --------
__device__ __align__(16) float g_xz[(size_t)T_STEPS * G4H];  // 128 MB precomputed input projections
__device__ __align__(16) float g_h[2][HDIM];                 // double-buffered hidden state
__device__ unsigned int g_bar;                               // grid barrier counter (reset by gemm kernel)

// ---------------------------------------------------------------------------
// Kernel 1: xz[t, :] = input_seq[t, :] @ W_ih^T + (b_ih + b_hh)
// Plain fp32 SIMT GEMM, 128x128 block tile, 8x8 per thread, BK=8.
// ---------------------------------------------------------------------------
__global__ __launch_bounds__(256) void xz_gemm(const float* __restrict__ A,
                                               const float* __restrict__ W,
                                               const float* __restrict__ b1,
                                               const float* __restrict__ b2) {
    if (blockIdx.x == 0 && blockIdx.y == 0 && threadIdx.x == 0) g_bar = 0u;  // reset barrier for lstm kernel

    __shared__ float a_sm[8][128];
    __shared__ float b_sm[8][128];

    const int tid = threadIdx.x;
    const int m0 = blockIdx.y * 128;
    const int n0 = blockIdx.x * 128;

    const int lr = tid >> 1;          // 0..127 row within tile
    const int lk = (tid & 1) * 4;     // 0 or 4
    const float* Ap = A + (size_t)(m0 + lr) * IDIM + lk;
    const float* Wp = W + (size_t)(n0 + lr) * IDIM + lk;

    const int tx = tid & 15;          // n sub-tile
    const int ty = tid >> 4;          // m sub-tile

    float acc[8][8];
#pragma unroll
    for (int i = 0; i < 8; i++)
#pragma unroll
        for (int j = 0; j < 8; j++) acc[i][j] = 0.f;

    for (int k0 = 0; k0 < IDIM; k0 += 8) {
        float4 av = *(const float4*)(Ap + k0);
        float4 wv = *(const float4*)(Wp + k0);
        __syncthreads();
        a_sm[lk + 0][lr] = av.x; a_sm[lk + 1][lr] = av.y;
        a_sm[lk + 2][lr] = av.z; a_sm[lk + 3][lr] = av.w;
        b_sm[lk + 0][lr] = wv.x; b_sm[lk + 1][lr] = wv.y;
        b_sm[lk + 2][lr] = wv.z; b_sm[lk + 3][lr] = wv.w;
        __syncthreads();
#pragma unroll
        for (int kk = 0; kk < 8; kk++) {
            float ar[8], br[8];
            *(float4*)&ar[0] = *(const float4*)&a_sm[kk][ty * 8];
            *(float4*)&ar[4] = *(const float4*)&a_sm[kk][ty * 8 + 4];
            *(float4*)&br[0] = *(const float4*)&b_sm[kk][tx * 8];
            *(float4*)&br[4] = *(const float4*)&b_sm[kk][tx * 8 + 4];
#pragma unroll
            for (int i = 0; i < 8; i++)
#pragma unroll
                for (int j = 0; j < 8; j++) acc[i][j] += ar[i] * br[j];
        }
    }

    // epilogue: add combined bias, vector stores
    float bias[8];
#pragma unroll
    for (int j = 0; j < 8; j++) {
        int n = n0 + tx * 8 + j;
        bias[j] = b1[n] + b2[n];
    }
#pragma unroll
    for (int i = 0; i < 8; i++) {
        int m = m0 + ty * 8 + i;
        float* Crow = g_xz + (size_t)m * G4H + n0 + tx * 8;
        float4 o0 = make_float4(acc[i][0] + bias[0], acc[i][1] + bias[1],
                                acc[i][2] + bias[2], acc[i][3] + bias[3]);
        float4 o1 = make_float4(acc[i][4] + bias[4], acc[i][5] + bias[5],
                                acc[i][6] + bias[6], acc[i][7] + bias[7]);
        *(float4*)(Crow + 0) = o0;
        *(float4*)(Crow + 4) = o1;
    }
}

// ---------------------------------------------------------------------------
// Kernel 2: persistent LSTM recurrence.
//  - 32 of 56 W_hh rows (bf16) in SMEM, 3 rows/warp in registers (96 uint/lane)
//    -> smem crossbar 260 KB/step -> 195 KB/step
//  - h staged through SMEM once per CTA (R12 win)
//  - barrier release fused into the atomic (red.release.gpu) -- no MEMBAR
// ---------------------------------------------------------------------------
__device__ __forceinline__ float bf_lo(unsigned u) { return __uint_as_float(u << 16); }
__device__ __forceinline__ float bf_hi(unsigned u) { return __uint_as_float(u & 0xffff0000u); }
__device__ __forceinline__ float sigmoidf_fast(float x) { return 1.f / (1.f + __expf(-x)); }
__device__ __forceinline__ float tanh_fast(float x) {
    float ax = fminf(fmaxf(x, -15.f), 15.f);
    float e = __expf(2.f * ax);
    return (e - 1.f) / (e + 1.f);
}

extern __shared__ __align__(16) unsigned char smem_dyn[];

__global__ __launch_bounds__(TPB, 1) void lstm_rec(const float* __restrict__ Whh) {
    // layout: weights (32 rows x 2048 bf16 = 131,072 B) | h stage (8,192 B) | z (224 B)
    __nv_bfloat16* w_sm = (__nv_bfloat16*)smem_dyn;
    float* h_sm = (float*)(smem_dyn + (size_t)NSMEM_ROWS * HDIM * 2);
    float* z_sm = h_sm + HDIM;

    const int b = blockIdx.x;
    const int tid = threadIdx.x;
    const int warp = tid >> 5;
    const int lane = tid & 31;
    const int jbase = b * JPC;

    // ---- prologue A: 32 smem rows (warp w slots 0..3 -> global rows w*7+0..3) ----
    for (int s = 0; s < NSMEM_ROWS; s++) {
        int w = s / SROWS_PER_WARP;
        int i = s - w * SROWS_PER_WARP;
        int r = w * RPW + i;               // global row (each warp's rows 0..3)
        int gate = r / JPC;
        int jl = r - gate * JPC;
        int j = jbase + jl;
        __nv_bfloat162* dst = (__nv_bfloat162*)(w_sm + (size_t)s * HDIM);
        if (j < HDIM) {
            const float4* src = (const float4*)(Whh + (size_t)(gate * HDIM + j) * HDIM);
            for (int k = tid; k < HDIM / 4; k += TPB) {
                float4 v = src[k];
                dst[2 * k]     = __floats2bfloat162_rn(v.x, v.y);
                dst[2 * k + 1] = __floats2bfloat162_rn(v.z, v.w);
            }
        } else {
            for (int k = tid; k < HDIM / 2; k += TPB)
                dst[k] = __floats2bfloat162_rn(0.f, 0.f);
        }
    }

    // ---- prologue B: 3 register rows per warp (rows w*7+4..6); lane's 64-col slice ----
    unsigned wreg[RROWS_PER_WARP][32];
#pragma unroll
    for (int rr = 0; rr < RROWS_PER_WARP; rr++) {
        int r = warp * RPW + SROWS_PER_WARP + rr;
        int gate = r / JPC;
        int jl = r - gate * JPC;
        int j = jbase + jl;
        if (j < HDIM) {
            const float* rowp = Whh + (size_t)(gate * HDIM + j) * HDIM;
#pragma unroll
            for (int c = 0; c < 8; c++) {
                int col0 = 8 * lane + 256 * c;
#pragma unroll
                for (int k = 0; k < 4; k++) {
                    float2 p = *(const float2*)(rowp + col0 + 2 * k);
                    __nv_bfloat162 bb = __floats2bfloat162_rn(p.x, p.y);
                    wreg[rr][4 * c + k] = *(unsigned*)&bb;
                }
            }
        } else {
#pragma unroll
            for (int k = 0; k < 32; k++) wreg[rr][k] = 0u;
        }
    }

    // zero initial hidden state slice (buffer 0 is read at t=0)
    if (tid < JPC && jbase + tid < HDIM) g_h[0][jbase + tid] = 0.f;

    float c_state = 0.f;
    unsigned int phase = 0;

    // prologue grid barrier: h zeros visible everywhere before step 0
    phase += NCTA;
    __syncthreads();
    if (tid == 0) {
        asm volatile("red.release.gpu.global.add.u32 [%0], 1;" :: "l"(&g_bar) : "memory");
        unsigned int v;
        do {
            asm volatile("ld.acquire.gpu.u32 %0, [%1];" : "=r"(v) : "l"(&g_bar));
            if (v >= phase) break;
            __nanosleep(32);
        } while (true);
    }
    __syncthreads();

    const int myrow = warp * RPW + lane;  // valid when lane < RPW

    for (int t = 0; t < T_STEPS; t++) {
        // this step's xz value for the row this lane will own (lane<7)
        float xzv = 0.f;
        if (lane < RPW) {
            int gate = myrow / JPC;
            int jl = myrow - gate * JPC;
            int j = jbase + jl;
            if (j < HDIM)
                xzv = __ldcg(&g_xz[(size_t)t * G4H + gate * HDIM + j]);
        }

        // ---- stage h into SMEM: 2 LDG.128 per thread (512 per CTA total) ----
        {
            const float4* hg = (const float4*)g_h[t & 1];
            float4 v0 = __ldcg(hg + tid * 2);
            float4 v1 = __ldcg(hg + tid * 2 + 1);
            ((float4*)h_sm)[tid * 2]     = v0;
            ((float4*)h_sm)[tid * 2 + 1] = v1;
        }
        __syncthreads();

        float acc[RPW];
#pragma unroll
        for (int r = 0; r < RPW; r++) acc[r] = 0.f;

        const uint4* wbase = (const uint4*)w_sm;  // 8 bf16 per uint4; row = 256 uint4
#pragma unroll
        for (int c = 0; c < 8; c++) {
            float4 h0 = *(const float4*)&h_sm[c * 256 + lane * 8];
            float4 h1 = *(const float4*)&h_sm[c * 256 + lane * 8 + 4];
            // 4 smem rows (global rows w*7+0..3)
#pragma unroll
            for (int r = 0; r < SROWS_PER_WARP; r++) {
                uint4 u = wbase[(warp * SROWS_PER_WARP + r) * 256 + lane + 32 * c];
                float a = acc[r];
                a += bf_lo(u.x) * h0.x; a += bf_hi(u.x) * h0.y;
                a += bf_lo(u.y) * h0.z; a += bf_hi(u.y) * h0.w;
                a += bf_lo(u.z) * h1.x; a += bf_hi(u.z) * h1.y;
                a += bf_lo(u.w) * h1.z; a += bf_hi(u.w) * h1.w;
                acc[r] = a;
            }
            // 3 register rows (global rows w*7+4..6)
#pragma unroll
            for (int rr = 0; rr < RROWS_PER_WARP; rr++) {
                unsigned ux = wreg[rr][4 * c + 0], uy = wreg[rr][4 * c + 1];
                unsigned uz = wreg[rr][4 * c + 2], uw = wreg[rr][4 * c + 3];
                float a = acc[SROWS_PER_WARP + rr];
                a += bf_lo(ux) * h0.x; a += bf_hi(ux) * h0.y;
                a += bf_lo(uy) * h0.z; a += bf_hi(uy) * h0.w;
                a += bf_lo(uz) * h1.x; a += bf_hi(uz) * h1.y;
                a += bf_lo(uw) * h1.z; a += bf_hi(uw) * h1.w;
                acc[SROWS_PER_WARP + rr] = a;
            }
        }

        // warp butterfly reduce each of the 7 row partials
#pragma unroll
        for (int r = 0; r < RPW; r++) {
            float a = acc[r];
#pragma unroll
            for (int off = 16; off; off >>= 1)
                a += __shfl_xor_sync(0xffffffffu, a, off);
            acc[r] = a;
        }

        if (lane < RPW) {
            float z = xzv;
#pragma unroll
            for (int r = 0; r < RPW; r++)
                if (lane == r) z += acc[r];
            z_sm[myrow] = z;
        }
        __syncthreads();   // z_sm complete before gate math reads it

        // gate math + state update for our 14 h-indices (warp 0, lanes 0..13)
        if (tid < JPC) {
            int j = jbase + tid;
            if (j < HDIM) {
                float zi = z_sm[tid];
                float zf = z_sm[JPC + tid];
                float zg = z_sm[2 * JPC + tid];
                float zo = z_sm[3 * JPC + tid];
                float ig = sigmoidf_fast(zi);
                float fg = sigmoidf_fast(zf);
                float gg = tanh_fast(zg);
                float og = sigmoidf_fast(zo);
                c_state = fg * c_state + ig * gg;
                g_h[(t + 1) & 1][j] = og * tanh_fast(c_state);
            }
        }
        __syncwarp();   // warp0: gate h-stores ordered before tid0's release below

        // grid barrier: release semantics fused into the arrive atomic
        // (syncwarp above orders lanes 0..13's h-stores before tid0's release op;
        //  cumulativity makes them visible to any CTA that acquires the counter)
        phase += NCTA;
        if (tid == 0) {
            asm volatile("red.release.gpu.global.add.u32 [%0], 1;" :: "l"(&g_bar) : "memory");
            unsigned int v;
            do {
                asm volatile("ld.acquire.gpu.u32 %0, [%1];" : "=r"(v) : "l"(&g_bar));
                if (v >= phase) break;
                __nanosleep(32);
            } while (true);
        }
        __syncthreads();   // release broadcast; also protects h_sm refill next step
    }
}

// ---------------------------------------------------------------------------
// Kernel 3: out = W_lin @ h_T + b_lin   (h_T is in g_h[0]: (4095+1)&1 == 0)
// ---------------------------------------------------------------------------
__global__ __launch_bounds__(256) void final_linear(const float* __restrict__ Wlin,
                                                    const float* __restrict__ blin,
                                                    float* __restrict__ out) {
    const float* h = g_h[0];
    const int o = blockIdx.x;
    const int tid = threadIdx.x;
    const float* wr = Wlin + (size_t)o * HDIM;

    float s = 0.f;
    for (int j = tid; j < HDIM; j += 256) s += wr[j] * h[j];

    __shared__ float red[8];
#pragma unroll
    for (int off = 16; off; off >>= 1) s += __shfl_xor_sync(0xffffffffu, s, off);
    if ((tid & 31) == 0) red[tid >> 5] = s;
    __syncthreads();
    if (tid < 32) {
        float v = (tid < 8) ? red[tid] : 0.f;
#pragma unroll
        for (int off = 16; off; off >>= 1) v += __shfl_xor_sync(0xffffffffu, v, off);
        if (tid == 0) out[o] = v + blin[o];
    }
}

// ---------------------------------------------------------------------------
extern "C" void kernel_launch(void* const* d_in, const int* in_sizes, int n_in,
                              void* d_out, int out_size) {
    const float* x    = (const float*)d_in[0];
    const float* Wih  = (const float*)d_in[1];
    const float* Whh  = (const float*)d_in[2];
    const float* bih  = (const float*)d_in[3];
    const float* bhh  = (const float*)d_in[4];
    const float* Wlin = (const float*)d_in[5];
    const float* blin = (const float*)d_in[6];
    float* out = (float*)d_out;

    // 32*2048*2 + 2048*4 + 56*4 = 131,072 + 8,192 + 224 = 139,488 B
    const size_t smem = (size_t)NSMEM_ROWS * HDIM * 2 + HDIM * 4 + RPC * 4;
    cudaFuncSetAttribute(lstm_rec, cudaFuncAttributeMaxDynamicSharedMemorySize, (int)smem);

    dim3 gg(G4H / 128, T_STEPS / 128);
    xz_gemm<<<gg, 256>>>(x, Wih, bih, bhh);        // also resets g_bar
    lstm_rec<<<NCTA, TPB, smem>>>(Whh);
    final_linear<<<ODIM, 256>>>(Wlin, blin, out);
}

// round 15
// speedup vs baseline: 1.9485x; 1.0118x over previous
#include <cuda_runtime.h>
#include <cuda_bf16.h>
#include <cstdint>

#define T_STEPS 4096
#define IDIM    512
#define HDIM    2048
#define ODIM    512
#define G4H     (4 * HDIM)   // 8192

#define NCTA 148   // persistent CTAs, 1 per SM
#define JPC  14    // h-indices per CTA: 148*14 = 2072 >= 2048
#define RPC  56    // rows of W_hh per CTA (4 gates * JPC)
#define RPG  7     // rows per group (8 groups of 2 warps)
#define SROWS_PER_GROUP 4
#define RROWS_PER_GROUP 3
#define NSMEM_ROWS (8 * SROWS_PER_GROUP)   // 32
#define TPB  512   // 16 warps: warp g (cols 0-1023) pairs with warp g+8 (cols 1024-2047)

// -------- persistent device state (no cudaMalloc allowed) --------
__device__ __align__(16) float g_xz[(size_t)T_STEPS * G4H];  // 128 MB precomputed input projections
__device__ __align__(16) float g_h[2][HDIM];                 // double-buffered hidden state
__device__ unsigned int g_bar;                               // grid barrier counter (reset by gemm kernel)

// ---------------------------------------------------------------------------
// Kernel 1: xz[t, :] = input_seq[t, :] @ W_ih^T + (b_ih + b_hh)
// ---------------------------------------------------------------------------
__global__ __launch_bounds__(256) void xz_gemm(const float* __restrict__ A,
                                               const float* __restrict__ W,
                                               const float* __restrict__ b1,
                                               const float* __restrict__ b2) {
    if (blockIdx.x == 0 && blockIdx.y == 0 && threadIdx.x == 0) g_bar = 0u;  // reset barrier for lstm kernel

    __shared__ float a_sm[8][128];
    __shared__ float b_sm[8][128];

    const int tid = threadIdx.x;
    const int m0 = blockIdx.y * 128;
    const int n0 = blockIdx.x * 128;

    const int lr = tid >> 1;          // 0..127 row within tile
    const int lk = (tid & 1) * 4;     // 0 or 4
    const float* Ap = A + (size_t)(m0 + lr) * IDIM + lk;
    const float* Wp = W + (size_t)(n0 + lr) * IDIM + lk;

    const int tx = tid & 15;          // n sub-tile
    const int ty = tid >> 4;          // m sub-tile

    float acc[8][8];
#pragma unroll
    for (int i = 0; i < 8; i++)
#pragma unroll
        for (int j = 0; j < 8; j++) acc[i][j] = 0.f;

    for (int k0 = 0; k0 < IDIM; k0 += 8) {
        float4 av = *(const float4*)(Ap + k0);
        float4 wv = *(const float4*)(Wp + k0);
        __syncthreads();
        a_sm[lk + 0][lr] = av.x; a_sm[lk + 1][lr] = av.y;
        a_sm[lk + 2][lr] = av.z; a_sm[lk + 3][lr] = av.w;
        b_sm[lk + 0][lr] = wv.x; b_sm[lk + 1][lr] = wv.y;
        b_sm[lk + 2][lr] = wv.z; b_sm[lk + 3][lr] = wv.w;
        __syncthreads();
#pragma unroll
        for (int kk = 0; kk < 8; kk++) {
            float ar[8], br[8];
            *(float4*)&ar[0] = *(const float4*)&a_sm[kk][ty * 8];
            *(float4*)&ar[4] = *(const float4*)&a_sm[kk][ty * 8 + 4];
            *(float4*)&br[0] = *(const float4*)&b_sm[kk][tx * 8];
            *(float4*)&br[4] = *(const float4*)&b_sm[kk][tx * 8 + 4];
#pragma unroll
            for (int i = 0; i < 8; i++)
#pragma unroll
                for (int j = 0; j < 8; j++) acc[i][j] += ar[i] * br[j];
        }
    }

    float bias[8];
#pragma unroll
    for (int j = 0; j < 8; j++) {
        int n = n0 + tx * 8 + j;
        bias[j] = b1[n] + b2[n];
    }
#pragma unroll
    for (int i = 0; i < 8; i++) {
        int m = m0 + ty * 8 + i;
        float* Crow = g_xz + (size_t)m * G4H + n0 + tx * 8;
        float4 o0 = make_float4(acc[i][0] + bias[0], acc[i][1] + bias[1],
                                acc[i][2] + bias[2], acc[i][3] + bias[3]);
        float4 o1 = make_float4(acc[i][4] + bias[4], acc[i][5] + bias[5],
                                acc[i][6] + bias[6], acc[i][7] + bias[7]);
        *(float4*)(Crow + 0) = o0;
        *(float4*)(Crow + 4) = o1;
    }
}

// profiling alignment pad (empty; shifts ncu -s 5 -c 1 onto lstm_rec)
__global__ void prof_pad() {}

// ---------------------------------------------------------------------------
// Kernel 2: persistent LSTM recurrence, 16 warps (column-split warp pairs).
//  Warp g (0..7) and warp g+8 own the SAME 7 rows, opposite 1024-col halves:
//  issue floor unchanged, crossbar unchanged (195 KB/step), but 4 warps/SMSP
//  hides LDS/SHFL/MUFU latency (2 warps/SMSP was the R13 binding constraint).
// ---------------------------------------------------------------------------
__device__ __forceinline__ float bf_lo(unsigned u) { return __uint_as_float(u << 16); }
__device__ __forceinline__ float bf_hi(unsigned u) { return __uint_as_float(u & 0xffff0000u); }
__device__ __forceinline__ float sigmoidf_fast(float x) { return 1.f / (1.f + __expf(-x)); }
__device__ __forceinline__ float tanh_fast(float x) {
    float ax = fminf(fmaxf(x, -15.f), 15.f);
    float e = __expf(2.f * ax);
    return (e - 1.f) / (e + 1.f);
}

extern __shared__ __align__(16) unsigned char smem_dyn[];

__global__ __launch_bounds__(TPB, 1) void lstm_rec(const float* __restrict__ Whh) {
    // layout: weights (32 rows x 2048 bf16 = 131,072 B) | h stage (8,192 B) | z partials (2x56 f32)
    __nv_bfloat16* w_sm = (__nv_bfloat16*)smem_dyn;
    float* h_sm = (float*)(smem_dyn + (size_t)NSMEM_ROWS * HDIM * 2);
    float* z_sm = h_sm + HDIM;                    // [2][RPC]

    const int b = blockIdx.x;
    const int tid = threadIdx.x;
    const int warp = tid >> 5;
    const int lane = tid & 31;
    const int grp  = warp & 7;        // row group 0..7
    const int half = warp >> 3;       // 0: cols 0-1023, 1: cols 1024-2047
    const int jbase = b * JPC;

    // ---- prologue A: 32 smem rows (group g slots 0..3 -> global rows g*7+0..3) ----
    for (int s = 0; s < NSMEM_ROWS; s++) {
        int g = s / SROWS_PER_GROUP;
        int i = s - g * SROWS_PER_GROUP;
        int r = g * RPG + i;
        int gate = r / JPC;
        int jl = r - gate * JPC;
        int j = jbase + jl;
        __nv_bfloat162* dst = (__nv_bfloat162*)(w_sm + (size_t)s * HDIM);
        if (j < HDIM) {
            const float4* src = (const float4*)(Whh + (size_t)(gate * HDIM + j) * HDIM);
            for (int k = tid; k < HDIM / 4; k += TPB) {
                float4 v = src[k];
                dst[2 * k]     = __floats2bfloat162_rn(v.x, v.y);
                dst[2 * k + 1] = __floats2bfloat162_rn(v.z, v.w);
            }
        } else {
            for (int k = tid; k < HDIM / 2; k += TPB)
                dst[k] = __floats2bfloat162_rn(0.f, 0.f);
        }
    }

    // ---- prologue B: 3 register rows per group (rows g*7+4..6), this warp's half ----
    unsigned wreg[RROWS_PER_GROUP][16];   // 16 uint = 32 bf16 cols per lane (quarter of a half... 1024/32/2)
#pragma unroll
    for (int rr = 0; rr < RROWS_PER_GROUP; rr++) {
        int r = grp * RPG + SROWS_PER_GROUP + rr;
        int gate = r / JPC;
        int jl = r - gate * JPC;
        int j = jbase + jl;
        if (j < HDIM) {
            const float* rowp = Whh + (size_t)(gate * HDIM + j) * HDIM;
#pragma unroll
            for (int c = 0; c < 4; c++) {
                int col0 = half * 1024 + 8 * lane + 256 * c;
#pragma unroll
                for (int k = 0; k < 4; k++) {
                    float2 p = *(const float2*)(rowp + col0 + 2 * k);
                    __nv_bfloat162 bb = __floats2bfloat162_rn(p.x, p.y);
                    wreg[rr][4 * c + k] = *(unsigned*)&bb;
                }
            }
        } else {
#pragma unroll
            for (int k = 0; k < 16; k++) wreg[rr][k] = 0u;
        }
    }

    // zero initial hidden state slice (buffer 0 is read at t=0)
    if (tid < JPC && jbase + tid < HDIM) g_h[0][jbase + tid] = 0.f;

    const bool gate_lane = (tid < JPC) && (jbase + tid < HDIM);
    float c_state = 0.f;
    unsigned int phase = 0;

    // prologue grid barrier
    phase += NCTA;
    __syncthreads();
    if (tid == 0) {
        asm volatile("red.release.gpu.global.add.u32 [%0], 1;" :: "l"(&g_bar) : "memory");
        unsigned int v;
        do {
            asm volatile("ld.acquire.gpu.u32 %0, [%1];" : "=r"(v) : "l"(&g_bar));
            if (v >= phase) break;
            __nanosleep(32);
        } while (true);
    }
    __syncthreads();

    for (int t = 0; t < T_STEPS; t++) {
        // gate lanes prefetch this step's 4 xz values (hidden under the matvec)
        float xz0 = 0.f, xz1 = 0.f, xz2 = 0.f, xz3 = 0.f;
        if (gate_lane) {
            const float* xp = g_xz + (size_t)t * G4H + jbase + tid;
            xz0 = __ldcg(xp);
            xz1 = __ldcg(xp + HDIM);
            xz2 = __ldcg(xp + 2 * HDIM);
            xz3 = __ldcg(xp + 3 * HDIM);
        }

        // ---- stage h into SMEM: 1 LDG.128 per thread ----
        {
            const float4* hg = (const float4*)g_h[t & 1];
            float4 v = __ldcg(hg + tid);
            ((float4*)h_sm)[tid] = v;
        }
        __syncthreads();

        float acc[RPG];
#pragma unroll
        for (int r = 0; r < RPG; r++) acc[r] = 0.f;

        const uint4* wbase = (const uint4*)w_sm;  // 8 bf16 per uint4; row = 256 uint4
#pragma unroll
        for (int c = 0; c < 4; c++) {             // 4 c-iters over this warp's 1024-col half
            const float* hp = &h_sm[half * 1024 + c * 256 + lane * 8];
            float4 h0 = *(const float4*)hp;
            float4 h1 = *(const float4*)(hp + 4);
            // 4 smem rows (global rows grp*7+0..3)
#pragma unroll
            for (int r = 0; r < SROWS_PER_GROUP; r++) {
                uint4 u = wbase[(grp * SROWS_PER_GROUP + r) * 256 + half * 128 + lane + 32 * c];
                float a = acc[r];
                a += bf_lo(u.x) * h0.x; a += bf_hi(u.x) * h0.y;
                a += bf_lo(u.y) * h0.z; a += bf_hi(u.y) * h0.w;
                a += bf_lo(u.z) * h1.x; a += bf_hi(u.z) * h1.y;
                a += bf_lo(u.w) * h1.z; a += bf_hi(u.w) * h1.w;
                acc[r] = a;
            }
            // 3 register rows (global rows grp*7+4..6)
#pragma unroll
            for (int rr = 0; rr < RROWS_PER_GROUP; rr++) {
                unsigned ux = wreg[rr][4 * c + 0], uy = wreg[rr][4 * c + 1];
                unsigned uz = wreg[rr][4 * c + 2], uw = wreg[rr][4 * c + 3];
                float a = acc[SROWS_PER_GROUP + rr];
                a += bf_lo(ux) * h0.x; a += bf_hi(ux) * h0.y;
                a += bf_lo(uy) * h0.z; a += bf_hi(uy) * h0.w;
                a += bf_lo(uz) * h1.x; a += bf_hi(uz) * h1.y;
                a += bf_lo(uw) * h1.z; a += bf_hi(uw) * h1.w;
                acc[SROWS_PER_GROUP + rr] = a;
            }
        }

        // warp butterfly reduce each of the 7 half-row partials
#pragma unroll
        for (int r = 0; r < RPG; r++) {
            float a = acc[r];
#pragma unroll
            for (int off = 16; off; off >>= 1)
                a += __shfl_xor_sync(0xffffffffu, a, off);
            acc[r] = a;
        }

        // lane r stores its half-partial for row grp*7+r
        if (lane < RPG) {
            float zp = 0.f;
#pragma unroll
            for (int r = 0; r < RPG; r++)
                if (lane == r) zp = acc[r];
            z_sm[half * RPC + grp * RPG + lane] = zp;
        }
        __syncthreads();   // both halves' partials visible

        // gate math + state update for our 14 h-indices (warp 0, lanes 0..13)
        if (gate_lane) {
            int j = jbase + tid;
            float zi = xz0 + z_sm[tid]            + z_sm[RPC + tid];
            float zf = xz1 + z_sm[JPC + tid]      + z_sm[RPC + JPC + tid];
            float zg = xz2 + z_sm[2 * JPC + tid]  + z_sm[RPC + 2 * JPC + tid];
            float zo = xz3 + z_sm[3 * JPC + tid]  + z_sm[RPC + 3 * JPC + tid];
            float ig = sigmoidf_fast(zi);
            float fg = sigmoidf_fast(zf);
            float gg = tanh_fast(zg);
            float og = sigmoidf_fast(zo);
            c_state = fg * c_state + ig * gg;
            g_h[(t + 1) & 1][j] = og * tanh_fast(c_state);
        }
        __syncwarp();   // warp0: gate h-stores ordered before tid0's release below

        // grid barrier: release fused into the arrive atomic
        phase += NCTA;
        if (tid == 0) {
            asm volatile("red.release.gpu.global.add.u32 [%0], 1;" :: "l"(&g_bar) : "memory");
            unsigned int v;
            do {
                asm volatile("ld.acquire.gpu.u32 %0, [%1];" : "=r"(v) : "l"(&g_bar));
                if (v >= phase) break;
                __nanosleep(32);
            } while (true);
        }
        __syncthreads();   // release broadcast; also protects h_sm/z_sm reuse next step
    }
}

// ---------------------------------------------------------------------------
// Kernel 3: out = W_lin @ h_T + b_lin   (h_T is in g_h[0]: (4095+1)&1 == 0)
// ---------------------------------------------------------------------------
__global__ __launch_bounds__(256) void final_linear(const float* __restrict__ Wlin,
                                                    const float* __restrict__ blin,
                                                    float* __restrict__ out) {
    const float* h = g_h[0];
    const int o = blockIdx.x;
    const int tid = threadIdx.x;
    const float* wr = Wlin + (size_t)o * HDIM;

    float s = 0.f;
    for (int j = tid; j < HDIM; j += 256) s += wr[j] * h[j];

    __shared__ float red[8];
#pragma unroll
    for (int off = 16; off; off >>= 1) s += __shfl_xor_sync(0xffffffffu, s, off);
    if ((tid & 31) == 0) red[tid >> 5] = s;
    __syncthreads();
    if (tid < 32) {
        float v = (tid < 8) ? red[tid] : 0.f;
#pragma unroll
        for (int off = 16; off; off >>= 1) v += __shfl_xor_sync(0xffffffffu, v, off);
        if (tid == 0) out[o] = v + blin[o];
    }
}

// ---------------------------------------------------------------------------
extern "C" void kernel_launch(void* const* d_in, const int* in_sizes, int n_in,
                              void* d_out, int out_size) {
    const float* x    = (const float*)d_in[0];
    const float* Wih  = (const float*)d_in[1];
    const float* Whh  = (const float*)d_in[2];
    const float* bih  = (const float*)d_in[3];
    const float* bhh  = (const float*)d_in[4];
    const float* Wlin = (const float*)d_in[5];
    const float* blin = (const float*)d_in[6];
    float* out = (float*)d_out;

    // 32*2048*2 + 2048*4 + 2*56*4 = 131,072 + 8,192 + 448 = 139,712 B
    const size_t smem = (size_t)NSMEM_ROWS * HDIM * 2 + HDIM * 4 + 2 * RPC * 4;
    cudaFuncSetAttribute(lstm_rec, cudaFuncAttributeMaxDynamicSharedMemorySize, (int)smem);

    dim3 gg(G4H / 128, T_STEPS / 128);
    xz_gemm<<<gg, 256>>>(x, Wih, bih, bhh);        // also resets g_bar
    // 4 empty pads: aligns ncu's "-s 5 -c 1" capture window onto lstm_rec
    prof_pad<<<1, 1>>>();
    prof_pad<<<1, 1>>>();
    prof_pad<<<1, 1>>>();
    prof_pad<<<1, 1>>>();
    lstm_rec<<<NCTA, TPB, smem>>>(Whh);
    final_linear<<<ODIM, 256>>>(Wlin, blin, out);
}